// round 15
// baseline (speedup 1.0000x reference)
#include <cuda_runtime.h>
#include <cuda_fp16.h>
#include <math_constants.h>

#define NB 4
#define NT 2048
#define NC 1024
#define NH 16
#define ND 64
#define N3 (3*NC)
#define NM (NB*NT)

// ---------------- device-global scratch ----------------
__device__ __half g_x16[NM*NC];       // x fp16
__device__ __half g_wa16[N3*NC];      // w_attn^T fp16 [3072][1024]
__device__ __half g_wp16[NC*NC];      // w_proj^T fp16 [1024][1024]
__device__ __half g_q16[NB*NH*NT*ND]; // q * 0.125 * log2(e)
__device__ __half g_k16[NB*NH*NT*ND];
__device__ __half g_v16[NB*NH*NT*ND];
__device__ __half g_o16[NM*NC];       // attention out fp16 [M][1024]

__device__ __forceinline__ unsigned smem_u32(const void* p){
    unsigned a;
    asm("{ .reg .u64 t; cvta.to.shared.u64 t, %1; cvt.u32.u64 %0, t; }" : "=r"(a) : "l"(p));
    return a;
}

#define CPA16(s, g)  asm volatile("cp.async.cg.shared.global [%0], [%1], 16;" :: "r"(s), "l"(g))
#define CP_COMMIT()  asm volatile("cp.async.commit_group;" ::: "memory")
#define CP_WAIT1()   asm volatile("cp.async.wait_group 1;" ::: "memory")
#define CP_WAIT0()   asm volatile("cp.async.wait_group 0;" ::: "memory")

#define LDSM4(r0, r1, r2, r3, a) \
    asm volatile("ldmatrix.sync.aligned.m8n8.x4.shared.b16 {%0,%1,%2,%3}, [%4];" \
        : "=r"(r0), "=r"(r1), "=r"(r2), "=r"(r3) : "r"(a))
#define LDSM4T(r0, r1, r2, r3, a) \
    asm volatile("ldmatrix.sync.aligned.m8n8.x4.trans.shared.b16 {%0,%1,%2,%3}, [%4];" \
        : "=r"(r0), "=r"(r1), "=r"(r2), "=r"(r3) : "r"(a))

#define MMAH(c, a, b0, b1) \
    asm volatile("mma.sync.aligned.m16n8k16.row.col.f32.f16.f16.f32 " \
        "{%0,%1,%2,%3}, {%4,%5,%6,%7}, {%8,%9}, {%0,%1,%2,%3};" \
        : "+f"((c)[0]), "+f"((c)[1]), "+f"((c)[2]), "+f"((c)[3]) \
        : "r"((a)[0]), "r"((a)[1]), "r"((a)[2]), "r"((a)[3]), "r"(b0), "r"(b1))

#define PKH2(d, hi, lo) asm("cvt.rn.f16x2.f32 %0, %1, %2;" : "=r"(d) : "f"(hi), "f"(lo))
#define EX2F(d, a)      asm("ex2.approx.f32 %0, %1;" : "=f"(d) : "f"(a))

#define QSCALE 0.1803368801111204f   // 0.125 * log2(e)

// ======================================================================
// fp32 -> fp16 conversions
// ======================================================================
__global__ void __launch_bounds__(256) k_cvt16(const float* __restrict__ in, int n4)
{
    int i = blockIdx.x * blockDim.x + threadIdx.x;
    if (i >= n4) return;
    float4 v = reinterpret_cast<const float4*>(in)[i];
    reinterpret_cast<__half2*>(g_x16)[i*2]   = __floats2half2_rn(v.x, v.y);
    reinterpret_cast<__half2*>(g_x16)[i*2+1] = __floats2half2_rn(v.z, v.w);
}

__global__ void __launch_bounds__(256) k_cvtT16(const float* __restrict__ W, int Nn, int which)
{
    __shared__ float tile[32][33];
    __half* th = (which == 0) ? g_wa16 : g_wp16;
    int tx = threadIdx.x, ty = threadIdx.y;
    int n0 = blockIdx.x*32, k0 = blockIdx.y*32;
#pragma unroll
    for (int i=0;i<4;i++)
        tile[ty + i*8][tx] = W[(k0 + ty + i*8)*Nn + n0 + tx];
    __syncthreads();
#pragma unroll
    for (int i=0;i<4;i++)
        th[(n0 + ty + i*8)*NC + k0 + tx] = __float2half(tile[tx][ty + i*8]);
}

// ======================================================================
// fp16 GEMM: CTA 128x128, 256 threads (8 warps, 64x32), BK=64,
// 3-stage cp.async (110KB -> 2 CTAs/SM), single barrier per chunk.
// ======================================================================
#define TILE_B (128*144)        // 18432 bytes
#define STG    (2*TILE_B)       // 36864 (A + B)
#define GSMEM  (3*STG)          // 110592
#define NCH    16               // K/64

__device__ __forceinline__ void ld_chunk16(
    unsigned st, const __half* A, const __half* B, int m0, int n0, int c, int tid)
{
    const int row = tid >> 1;
    const int ch0 = (tid & 1) * 4;
    const long aoff = (long)(m0 + row)*NC + c*64 + ch0*8;
    const long boff = (long)(n0 + row)*NC + c*64 + ch0*8;
    const unsigned sr = st + row*144 + ch0*16;
#pragma unroll
    for (int j=0;j<4;j++){
        CPA16(sr + j*16,          (const char*)(A + aoff + j*8));
        CPA16(sr + TILE_B + j*16, (const char*)(B + boff + j*8));
    }
    CP_COMMIT();
}

__global__ void __launch_bounds__(256) k_gemm16(
    const float* __restrict__ bias, float* __restrict__ outp, int mode)
{
    extern __shared__ __align__(128) char smem[];
    const __half* A = (mode == 0) ? g_x16 : g_o16;
    const __half* B = (mode == 0) ? g_wa16 : g_wp16;
    const unsigned sb = smem_u32(smem);
    const int tid = threadIdx.x;
    const int wid = tid >> 5, lane = tid & 31;
    const int wm = wid >> 2, wn = wid & 3;
    const int m0 = blockIdx.y << 7;
    const int n0 = blockIdx.x << 7;

    float c[4][4][4];
#pragma unroll
    for (int i=0;i<4;i++)
#pragma unroll
        for (int j=0;j<4;j++){ c[i][j][0]=0.f; c[i][j][1]=0.f; c[i][j][2]=0.f; c[i][j][3]=0.f; }

    const unsigned a_base = (wm*64 + (lane & 15))*144 + (lane >> 4)*16;
    const unsigned b_base = (wn*32 + (lane & 7) + ((lane >> 1) & 8))*144 + (lane & 8)*2;

    ld_chunk16(sb,       A, B, m0, n0, 0, tid);
    ld_chunk16(sb + STG, A, B, m0, n0, 1, tid);

    for (int cc = 0; cc < NCH; cc++){
        if (cc == NCH-1) { CP_WAIT0(); } else { CP_WAIT1(); }
        __syncthreads();
        if (cc + 2 < NCH)
            ld_chunk16(sb + ((cc+2)%3)*STG, A, B, m0, n0, cc + 2, tid);
        const unsigned st = sb + (cc%3)*STG;
#pragma unroll
        for (int ks = 0; ks < 4; ks++){
            unsigned ar[4][4], br[2][4];
#pragma unroll
            for (int mi=0; mi<4; mi++)
                LDSM4(ar[mi][0], ar[mi][1], ar[mi][2], ar[mi][3],
                      st + a_base + mi*16*144 + ks*32);
#pragma unroll
            for (int nb=0; nb<2; nb++)
                LDSM4(br[nb][0], br[nb][1], br[nb][2], br[nb][3],
                      st + TILE_B + b_base + nb*16*144 + ks*32);
#pragma unroll
            for (int mi=0; mi<4; mi++){
                MMAH(c[mi][0], ar[mi], br[0][0], br[0][1]);
                MMAH(c[mi][1], ar[mi], br[0][2], br[0][3]);
                MMAH(c[mi][2], ar[mi], br[1][0], br[1][1]);
                MMAH(c[mi][3], ar[mi], br[1][2], br[1][3]);
            }
        }
        // no trailing barrier: next iteration's leading barrier protects
        // stage (cc+3)%3 against its readers (this iteration's compute).
    }

    const int group = lane >> 2, tig = lane & 3;
#pragma unroll
    for (int mi=0; mi<4; mi++){
#pragma unroll
        for (int half=0; half<2; half++){
            const int m = m0 + wm*64 + mi*16 + group + half*8;
#pragma unroll
            for (int nf=0; nf<4; nf++){
                const int n = n0 + wn*32 + nf*8 + tig*2;
                float vx = c[mi][nf][half*2+0] + __ldg(&bias[n]);
                float vy = c[mi][nf][half*2+1] + __ldg(&bias[n+1]);
                if (mode == 1){
                    float2 v = {vx, vy};
                    *reinterpret_cast<float2*>(outp + (size_t)m*NC + n) = v;
                } else {
                    const int which = n >> 10;
                    const int cn = n & 1023;
                    const int h = cn >> 6, d = cn & 63;
                    const int bb = m >> 11, t = m & 2047;
                    __half* dst = (which == 0) ? g_q16 : (which == 1) ? g_k16 : g_v16;
                    if (which == 0){ vx *= QSCALE; vy *= QSCALE; }
                    *reinterpret_cast<__half2*>(dst + ((bb*NH + h)*NT + t)*ND + d)
                        = __floats2half2_rn(vx, vy);
                }
            }
        }
    }
}

// ======================================================================
// Tensor-core flash attention (no max-sub; l via ones-column of V)
// CTA: 128 queries x one (b,h); 8 warps each own 16 q rows.
// 128-key stages (two 64-key compute halves), 2-stage double buffer:
// ONE wait + ONE barrier per 128 keys.
// ======================================================================
#define SQ_OFF 0
#define SQ_STR 144
#define SK_OFF 18432
#define KSTG   18432                 // 128*144
#define SV_OFF (SK_OFF + 2*KSTG)     // 55296
#define VSTG   22528                 // 128*176
#define ASMEM  (SV_OFF + 2*VSTG)     // 100352

__device__ __forceinline__ void ld_kv128(unsigned kb, unsigned vb,
    const __half* kg, const __half* vg, int kt, int tid)
{
    const int r  = tid >> 1;                 // 0..127
    const int c4 = (tid & 1) * 4;            // chunk 0..3 or 4..7
    const char* kp = (const char*)(kg + (size_t)(kt*128 + r)*ND) + c4*16;
    const char* vp = (const char*)(vg + (size_t)(kt*128 + r)*ND) + c4*16;
#pragma unroll
    for (int j=0;j<4;j++){
        CPA16(kb + r*144 + (c4+j)*16, kp + j*16);
        CPA16(vb + r*176 + (c4+j)*16, vp + j*16);
    }
}

__global__ void __launch_bounds__(256) k_attn16()
{
    extern __shared__ __align__(128) char smem[];
    const unsigned sb = smem_u32(smem);
    const int tid = threadIdx.x;
    const int wid = tid >> 5, lane = tid & 31;
    const int qb = 15 - blockIdx.x;             // heavy blocks first
    const int bh = blockIdx.y;
    const int bb = bh >> 4, h = bh & 15;

    const __half* qg = g_q16 + (size_t)(bh*NT + qb*128)*ND;
    const __half* kg = g_k16 + (size_t)bh*NT*ND;
    const __half* vg = g_v16 + (size_t)bh*NT*ND;

    // V constant columns 64..79: col 64 = 1.0, rest 0 (both stages)
    for (int idx = tid; idx < 2*128; idx += 256){
        const int s = idx >> 7, r = idx & 127;
        uint4 one0 = {0x00003C00u, 0u, 0u, 0u};
        uint4 zero = {0u, 0u, 0u, 0u};
        *reinterpret_cast<uint4*>(smem + SV_OFF + s*VSTG + r*176 + 128) = one0;
        *reinterpret_cast<uint4*>(smem + SV_OFF + s*VSTG + r*176 + 144) = zero;
    }

    // prologue: Q + tile 0 (K/V) in one group
#pragma unroll
    for (int i=0;i<4;i++){
        int idx = tid + i*256;
        int row = idx >> 3, ch = idx & 7;
        CPA16(sb + SQ_OFF + row*SQ_STR + ch*16, (const char*)(qg + row*ND) + ch*16);
    }
    ld_kv128(sb + SK_OFF, sb + SV_OFF, kg, vg, 0, tid);
    CP_COMMIT();
    CP_WAIT0();
    __syncthreads();

    // Q A-fragments (persist across key tiles)
    unsigned aq[4][4];
    const unsigned qa = sb + SQ_OFF + (wid*16 + (lane & 15))*SQ_STR + (lane >> 4)*16;
#pragma unroll
    for (int ks=0; ks<4; ks++)
        LDSM4(aq[ks][0], aq[ks][1], aq[ks][2], aq[ks][3], qa + ks*32);

    float o_acc[9][4];
#pragma unroll
    for (int o=0;o<9;o++){ o_acc[o][0]=0.f; o_acc[o][1]=0.f; o_acc[o][2]=0.f; o_acc[o][3]=0.f; }

    const int row0 = qb*128 + wid*16 + (lane >> 2);
    const int ktmax = qb + 1;                  // 128-key tiles

    for (int kt = 0; kt < ktmax; kt++){
        if (kt > 0){
            CP_WAIT0();
            __syncthreads();
        }
        if (kt + 1 < ktmax){
            ld_kv128(sb + SK_OFF + ((kt+1)&1)*KSTG, sb + SV_OFF + ((kt+1)&1)*VSTG,
                     kg, vg, kt+1, tid);
            CP_COMMIT();
        }

        const unsigned kbs = sb + SK_OFF + (kt&1)*KSTG;
        const unsigned vbs = sb + SV_OFF + (kt&1)*VSTG;
        const bool diag = (kt == qb);

#pragma unroll
        for (int hf = 0; hf < 2; hf++){
            // GEMM1: S' = Q·K^T over keys [kt*128 + hf*64, +64)
            float cS[8][4];
#pragma unroll
            for (int nf=0;nf<8;nf++){ cS[nf][0]=0.f; cS[nf][1]=0.f; cS[nf][2]=0.f; cS[nf][3]=0.f; }
            const unsigned kb_lane = kbs + hf*64*144
                + ((lane & 7) + ((lane >> 1) & 8))*144 + (lane & 8)*2;
            {
                unsigned bkf[2][4];
                LDSM4(bkf[0][0], bkf[0][1], bkf[0][2], bkf[0][3], kb_lane);
#pragma unroll
                for (int s = 0; s < 16; s++){
                    const int cur = s & 1, nxt = cur ^ 1;
                    if (s < 15){
                        const int s1 = s + 1;
                        LDSM4(bkf[nxt][0], bkf[nxt][1], bkf[nxt][2], bkf[nxt][3],
                              kb_lane + (s1 & 3)*16*144 + (s1 >> 2)*32);
                    }
                    const int ks = s >> 2, nb = s & 3;
                    MMAH(cS[2*nb],   aq[ks], bkf[cur][0], bkf[cur][1]);
                    MMAH(cS[2*nb+1], aq[ks], bkf[cur][2], bkf[cur][3]);
                }
            }

            // softmax: P = 2^(S'), causal mask on the diagonal tile
            unsigned plo[8], phi[8];
#pragma unroll
            for (int nf=0; nf<8; nf++){
                float s0 = cS[nf][0], s1 = cS[nf][1], s2 = cS[nf][2], s3 = cS[nf][3];
                if (diag){
                    const int c0 = kt*128 + hf*64 + nf*8 + (lane & 3)*2;
                    if (c0     > row0)     s0 = -1e4f;
                    if (c0 + 1 > row0)     s1 = -1e4f;
                    if (c0     > row0 + 8) s2 = -1e4f;
                    if (c0 + 1 > row0 + 8) s3 = -1e4f;
                }
                float e0,e1,e2,e3;
                EX2F(e0, s0); EX2F(e1, s1); EX2F(e2, s2); EX2F(e3, s3);
                PKH2(plo[nf], e1, e0);
                PKH2(phi[nf], e3, e2);
            }

            // GEMM2: O_ext += P · [V | 1 0...]
            const unsigned vb_lane = vbs + hf*64*176
                + ((lane & 7) + (lane & 8))*176 + ((lane >> 4) & 1)*16;
#pragma unroll
            for (int j=0; j<4; j++){
                unsigned a[4] = {plo[2*j], phi[2*j], plo[2*j+1], phi[2*j+1]};
                unsigned vt[2][4];
                LDSM4T(vt[0][0], vt[0][1], vt[0][2], vt[0][3], vb_lane + j*16*176);
#pragma unroll
                for (int dd=0; dd<5; dd++){
                    const int cur = dd & 1, nxt = cur ^ 1;
                    if (dd < 4)
                        LDSM4T(vt[nxt][0], vt[nxt][1], vt[nxt][2], vt[nxt][3],
                               vb_lane + j*16*176 + (dd+1)*32);
                    MMAH(o_acc[2*dd], a, vt[cur][0], vt[cur][1]);
                    if (dd < 4)
                        MMAH(o_acc[2*dd+1], a, vt[cur][2], vt[cur][3]);
                }
            }
        }
    }

    // epilogue
    const float l0 = __shfl_sync(0xffffffffu, o_acc[8][0], lane & ~3);
    const float l1 = __shfl_sync(0xffffffffu, o_acc[8][2], lane & ~3);
    const float i0 = 1.0f / l0;
    const float i1 = 1.0f / l1;
#pragma unroll
    for (int o=0; o<8; o++){
        const int col = h*64 + o*8 + (lane & 3)*2;
        *reinterpret_cast<__half2*>(g_o16 + (size_t)(bb*NT + row0)*NC + col)
            = __floats2half2_rn(o_acc[o][0]*i0, o_acc[o][1]*i0);
        *reinterpret_cast<__half2*>(g_o16 + (size_t)(bb*NT + row0 + 8)*NC + col)
            = __floats2half2_rn(o_acc[o][2]*i1, o_acc[o][3]*i1);
    }
}

// ======================================================================
extern "C" void kernel_launch(void* const* d_in, const int* in_sizes, int n_in,
                              void* d_out, int out_size)
{
    const float* x      = (const float*)d_in[0];
    const float* w_attn = (const float*)d_in[1];
    const float* b_attn = (const float*)d_in[2];
    const float* w_proj = (const float*)d_in[3];
    const float* b_proj = (const float*)d_in[4];
    float* out = (float*)d_out;

    cudaFuncSetAttribute(k_gemm16, cudaFuncAttributeMaxDynamicSharedMemorySize, GSMEM);
    cudaFuncSetAttribute(k_attn16, cudaFuncAttributeMaxDynamicSharedMemorySize, ASMEM);

    k_cvt16 <<<(NM*NC/4 + 255)/256, 256>>>(x, NM*NC/4);
    k_cvtT16<<<dim3(N3/32, NC/32), dim3(32,8)>>>(w_attn, N3, 0);
    k_cvtT16<<<dim3(NC/32, NC/32), dim3(32,8)>>>(w_proj, NC, 1);

    k_gemm16<<<dim3(N3/128, NM/128), 256, GSMEM>>>(b_attn, nullptr, 0);
    k_attn16<<<dim3(16, NB*NH), 256, ASMEM>>>();
    k_gemm16<<<dim3(NC/128, NM/128), 256, GSMEM>>>(b_proj, out, 1);
}

// round 16
// speedup vs baseline: 1.0274x; 1.0274x over previous
#include <cuda_runtime.h>
#include <cuda_fp16.h>
#include <math_constants.h>

#define NB 4
#define NT 2048
#define NC 1024
#define NH 16
#define ND 64
#define N3 (3*NC)
#define NM (NB*NT)

// ---------------- device-global scratch ----------------
__device__ __half g_x16[NM*NC];       // x fp16
__device__ __half g_wa16[N3*NC];      // w_attn^T fp16 [3072][1024]
__device__ __half g_wp16[NC*NC];      // w_proj^T fp16 [1024][1024]
__device__ __half g_q16[NB*NH*NT*ND]; // q * 0.125 * log2(e)
__device__ __half g_k16[NB*NH*NT*ND];
__device__ __half g_v16[NB*NH*NT*ND];
__device__ __half g_o16[NM*NC];       // attention out fp16 [M][1024]

__device__ __forceinline__ unsigned smem_u32(const void* p){
    unsigned a;
    asm("{ .reg .u64 t; cvta.to.shared.u64 t, %1; cvt.u32.u64 %0, t; }" : "=r"(a) : "l"(p));
    return a;
}

#define CPA16(s, g)  asm volatile("cp.async.cg.shared.global [%0], [%1], 16;" :: "r"(s), "l"(g))
#define CP_COMMIT()  asm volatile("cp.async.commit_group;" ::: "memory")
#define CP_WAIT1()   asm volatile("cp.async.wait_group 1;" ::: "memory")
#define CP_WAIT0()   asm volatile("cp.async.wait_group 0;" ::: "memory")

#define LDSM4(r0, r1, r2, r3, a) \
    asm volatile("ldmatrix.sync.aligned.m8n8.x4.shared.b16 {%0,%1,%2,%3}, [%4];" \
        : "=r"(r0), "=r"(r1), "=r"(r2), "=r"(r3) : "r"(a))
#define LDSM4T(r0, r1, r2, r3, a) \
    asm volatile("ldmatrix.sync.aligned.m8n8.x4.trans.shared.b16 {%0,%1,%2,%3}, [%4];" \
        : "=r"(r0), "=r"(r1), "=r"(r2), "=r"(r3) : "r"(a))

#define MMAH(c, a, b0, b1) \
    asm volatile("mma.sync.aligned.m16n8k16.row.col.f32.f16.f16.f32 " \
        "{%0,%1,%2,%3}, {%4,%5,%6,%7}, {%8,%9}, {%0,%1,%2,%3};" \
        : "+f"((c)[0]), "+f"((c)[1]), "+f"((c)[2]), "+f"((c)[3]) \
        : "r"((a)[0]), "r"((a)[1]), "r"((a)[2]), "r"((a)[3]), "r"(b0), "r"(b1))

#define PKH2(d, hi, lo) asm("cvt.rn.f16x2.f32 %0, %1, %2;" : "=r"(d) : "f"(hi), "f"(lo))
#define EX2F(d, a)      asm("ex2.approx.f32 %0, %1;" : "=f"(d) : "f"(a))

#define QSCALE 0.1803368801111204f   // 0.125 * log2(e)

// ======================================================================
// fp32 -> fp16 conversions
// ======================================================================
__global__ void __launch_bounds__(256) k_cvt16(const float* __restrict__ in, int n4)
{
    int i = blockIdx.x * blockDim.x + threadIdx.x;
    if (i >= n4) return;
    float4 v = reinterpret_cast<const float4*>(in)[i];
    reinterpret_cast<__half2*>(g_x16)[i*2]   = __floats2half2_rn(v.x, v.y);
    reinterpret_cast<__half2*>(g_x16)[i*2+1] = __floats2half2_rn(v.z, v.w);
}

__global__ void __launch_bounds__(256) k_cvtT16(const float* __restrict__ W, int Nn, int which)
{
    __shared__ float tile[32][33];
    __half* th = (which == 0) ? g_wa16 : g_wp16;
    int tx = threadIdx.x, ty = threadIdx.y;
    int n0 = blockIdx.x*32, k0 = blockIdx.y*32;
#pragma unroll
    for (int i=0;i<4;i++)
        tile[ty + i*8][tx] = W[(k0 + ty + i*8)*Nn + n0 + tx];
    __syncthreads();
#pragma unroll
    for (int i=0;i<4;i++)
        th[(n0 + ty + i*8)*NC + k0 + tx] = __float2half(tile[tx][ty + i*8]);
}

// ======================================================================
// fp16 GEMM (R14 exact): CTA 128x128, 256 threads (8 warps, 64x32), BK=64,
// 3-stage cp.async (110KB -> 2 CTAs/SM), fragment ping-pong.
// ======================================================================
#define TILE_B (128*144)        // 18432 bytes
#define STG    (2*TILE_B)       // 36864 (A + B)
#define GSMEM  (3*STG)          // 110592
#define NCH    16               // K/64

__device__ __forceinline__ void ld_chunk16(
    unsigned st, const __half* A, const __half* B, int m0, int n0, int c, int tid)
{
    const int row = tid >> 1;
    const int ch0 = (tid & 1) * 4;
    const long aoff = (long)(m0 + row)*NC + c*64 + ch0*8;
    const long boff = (long)(n0 + row)*NC + c*64 + ch0*8;
    const unsigned sr = st + row*144 + ch0*16;
#pragma unroll
    for (int j=0;j<4;j++){
        CPA16(sr + j*16,          (const char*)(A + aoff + j*8));
        CPA16(sr + TILE_B + j*16, (const char*)(B + boff + j*8));
    }
    CP_COMMIT();
}

__global__ void __launch_bounds__(256) k_gemm16(
    const float* __restrict__ bias, float* __restrict__ outp, int mode)
{
    extern __shared__ __align__(128) char smem[];
    const __half* A = (mode == 0) ? g_x16 : g_o16;
    const __half* B = (mode == 0) ? g_wa16 : g_wp16;
    const unsigned sb = smem_u32(smem);
    const int tid = threadIdx.x;
    const int wid = tid >> 5, lane = tid & 31;
    const int wm = wid >> 2, wn = wid & 3;
    const int m0 = blockIdx.y << 7;
    const int n0 = blockIdx.x << 7;

    float c[4][4][4];
#pragma unroll
    for (int i=0;i<4;i++)
#pragma unroll
        for (int j=0;j<4;j++){ c[i][j][0]=0.f; c[i][j][1]=0.f; c[i][j][2]=0.f; c[i][j][3]=0.f; }

    const unsigned a_base = (wm*64 + (lane & 15))*144 + (lane >> 4)*16;
    const unsigned b_base = (wn*32 + (lane & 7) + ((lane >> 1) & 8))*144 + (lane & 8)*2;

    ld_chunk16(sb,       A, B, m0, n0, 0, tid);
    ld_chunk16(sb + STG, A, B, m0, n0, 1, tid);

    for (int cc = 0; cc < NCH; cc++){
        if (cc == NCH-1) { CP_WAIT0(); } else { CP_WAIT1(); }
        __syncthreads();
        if (cc + 2 < NCH)
            ld_chunk16(sb + ((cc+2)%3)*STG, A, B, m0, n0, cc + 2, tid);
        const unsigned st = sb + (cc%3)*STG;

        unsigned ar[2][4][4], br[2][2][4];
#pragma unroll
        for (int mi=0; mi<4; mi++)
            LDSM4(ar[0][mi][0], ar[0][mi][1], ar[0][mi][2], ar[0][mi][3],
                  st + a_base + mi*16*144);
#pragma unroll
        for (int nb=0; nb<2; nb++)
            LDSM4(br[0][nb][0], br[0][nb][1], br[0][nb][2], br[0][nb][3],
                  st + TILE_B + b_base + nb*16*144);
#pragma unroll
        for (int ks = 0; ks < 4; ks++){
            const int cur = ks & 1, nxt = cur ^ 1;
            if (ks < 3){
#pragma unroll
                for (int mi=0; mi<4; mi++)
                    LDSM4(ar[nxt][mi][0], ar[nxt][mi][1], ar[nxt][mi][2], ar[nxt][mi][3],
                          st + a_base + mi*16*144 + (ks+1)*32);
#pragma unroll
                for (int nb=0; nb<2; nb++)
                    LDSM4(br[nxt][nb][0], br[nxt][nb][1], br[nxt][nb][2], br[nxt][nb][3],
                          st + TILE_B + b_base + nb*16*144 + (ks+1)*32);
            }
#pragma unroll
            for (int mi=0; mi<4; mi++){
                MMAH(c[mi][0], ar[cur][mi], br[cur][0][0], br[cur][0][1]);
                MMAH(c[mi][1], ar[cur][mi], br[cur][0][2], br[cur][0][3]);
                MMAH(c[mi][2], ar[cur][mi], br[cur][1][0], br[cur][1][1]);
                MMAH(c[mi][3], ar[cur][mi], br[cur][1][2], br[cur][1][3]);
            }
        }
        __syncthreads();
    }

    const int group = lane >> 2, tig = lane & 3;
#pragma unroll
    for (int mi=0; mi<4; mi++){
#pragma unroll
        for (int half=0; half<2; half++){
            const int m = m0 + wm*64 + mi*16 + group + half*8;
#pragma unroll
            for (int nf=0; nf<4; nf++){
                const int n = n0 + wn*32 + nf*8 + tig*2;
                float vx = c[mi][nf][half*2+0] + __ldg(&bias[n]);
                float vy = c[mi][nf][half*2+1] + __ldg(&bias[n+1]);
                if (mode == 1){
                    float2 v = {vx, vy};
                    *reinterpret_cast<float2*>(outp + (size_t)m*NC + n) = v;
                } else {
                    const int which = n >> 10;
                    const int cn = n & 1023;
                    const int h = cn >> 6, d = cn & 63;
                    const int bb = m >> 11, t = m & 2047;
                    __half* dst = (which == 0) ? g_q16 : (which == 1) ? g_k16 : g_v16;
                    if (which == 0){ vx *= QSCALE; vy *= QSCALE; }
                    *reinterpret_cast<__half2*>(dst + ((bb*NH + h)*NT + t)*ND + d)
                        = __floats2half2_rn(vx, vy);
                }
            }
        }
    }
}

// ======================================================================
// Tensor-core flash attention: l computed on the FMA pipe (fp32 sums of
// the exponentials) — no ones-column, V stride 144, o_acc[8].
// CTA: 128 queries x one (b,h); 8 warps each own 16 q rows; 64-key tiles.
// ======================================================================
#define SQ_OFF 0
#define SQ_STR 144
#define SK_OFF 18432
#define KSTG   9216                  // 64*144
#define SV_OFF (SK_OFF + 3*KSTG)     // 46080
#define VSTG   9216                  // 64*144
#define ASMEM  (SV_OFF + 3*VSTG)     // 73728

__device__ __forceinline__ void ld_kv(unsigned kb, unsigned vb,
    const __half* kg, const __half* vg, int kt, int tid)
{
    const int r  = tid >> 2;
    const int c2 = (tid & 3) * 2;
    const char* kp = (const char*)(kg + (size_t)(kt*64 + r)*ND) + c2*16;
    const char* vp = (const char*)(vg + (size_t)(kt*64 + r)*ND) + c2*16;
    CPA16(kb + r*144 + c2*16,      kp);
    CPA16(kb + r*144 + c2*16 + 16, kp + 16);
    CPA16(vb + r*144 + c2*16,      vp);
    CPA16(vb + r*144 + c2*16 + 16, vp + 16);
}

__global__ void __launch_bounds__(256) k_attn16()
{
    extern __shared__ __align__(128) char smem[];
    const unsigned sb = smem_u32(smem);
    const int tid = threadIdx.x;
    const int wid = tid >> 5, lane = tid & 31;
    const int qb = 15 - blockIdx.x;             // heavy blocks first
    const int bh = blockIdx.y;
    const int bb = bh >> 4, h = bh & 15;

    const __half* qg = g_q16 + (size_t)(bh*NT + qb*128)*ND;
    const __half* kg = g_k16 + (size_t)bh*NT*ND;
    const __half* vg = g_v16 + (size_t)bh*NT*ND;

    // prologue: Q + K0/V0 as group 0; K1/V1 as group 1
#pragma unroll
    for (int i=0;i<4;i++){
        int idx = tid + i*256;
        int row = idx >> 3, ch = idx & 7;
        CPA16(sb + SQ_OFF + row*SQ_STR + ch*16, (const char*)(qg + row*ND) + ch*16);
    }
    ld_kv(sb + SK_OFF, sb + SV_OFF, kg, vg, 0, tid);
    CP_COMMIT();
    ld_kv(sb + SK_OFF + KSTG, sb + SV_OFF + VSTG, kg, vg, 1, tid);
    CP_COMMIT();
    CP_WAIT1();
    __syncthreads();

    // Q A-fragments (persist across key tiles)
    unsigned aq[4][4];
    const unsigned qa = sb + SQ_OFF + (wid*16 + (lane & 15))*SQ_STR + (lane >> 4)*16;
#pragma unroll
    for (int ks=0; ks<4; ks++)
        LDSM4(aq[ks][0], aq[ks][1], aq[ks][2], aq[ks][3], qa + ks*32);

    float o_acc[8][4];
#pragma unroll
    for (int o=0;o<8;o++){ o_acc[o][0]=0.f; o_acc[o][1]=0.f; o_acc[o][2]=0.f; o_acc[o][3]=0.f; }
    float lsum_lo = 0.f, lsum_hi = 0.f;

    const int row0 = qb*128 + wid*16 + (lane >> 2);
    const int ktmax = 2*qb + 2;

    for (int kt = 0; kt < ktmax; kt++){
        if (kt > 0){
            if (kt == ktmax-1) { CP_WAIT0(); } else { CP_WAIT1(); }
            __syncthreads();
        }
        if (kt + 2 < ktmax){
            ld_kv(sb + SK_OFF + ((kt+2)%3)*KSTG, sb + SV_OFF + ((kt+2)%3)*VSTG,
                  kg, vg, kt+2, tid);
            CP_COMMIT();
        }

        const unsigned kbs = sb + SK_OFF + (kt%3)*KSTG;
        const unsigned vbs = sb + SV_OFF + (kt%3)*VSTG;

        // GEMM1: S' = Q·K^T, 16 ping-ponged steps
        float cS[8][4];
#pragma unroll
        for (int nf=0;nf<8;nf++){ cS[nf][0]=0.f; cS[nf][1]=0.f; cS[nf][2]=0.f; cS[nf][3]=0.f; }
        const unsigned kb_lane = kbs + ((lane & 7) + ((lane >> 1) & 8))*144 + (lane & 8)*2;
        {
            unsigned bkf[2][4];
            LDSM4(bkf[0][0], bkf[0][1], bkf[0][2], bkf[0][3], kb_lane);
#pragma unroll
            for (int s = 0; s < 16; s++){
                const int cur = s & 1, nxt = cur ^ 1;
                if (s < 15){
                    const int s1 = s + 1;
                    LDSM4(bkf[nxt][0], bkf[nxt][1], bkf[nxt][2], bkf[nxt][3],
                          kb_lane + (s1 & 3)*16*144 + (s1 >> 2)*32);
                }
                const int ks = s >> 2, nb = s & 3;
                MMAH(cS[2*nb],   aq[ks], bkf[cur][0], bkf[cur][1]);
                MMAH(cS[2*nb+1], aq[ks], bkf[cur][2], bkf[cur][3]);
            }
        }

        // softmax: P = 2^(S'); l accumulated in fp32 on the FMA pipe
        const bool masked = (kt >= 2*qb);
        unsigned plo[8], phi[8];
#pragma unroll
        for (int nf=0; nf<8; nf++){
            float s0 = cS[nf][0], s1 = cS[nf][1], s2 = cS[nf][2], s3 = cS[nf][3];
            if (masked){
                const int c0 = kt*64 + nf*8 + (lane & 3)*2;
                if (c0     > row0)     s0 = -1e4f;
                if (c0 + 1 > row0)     s1 = -1e4f;
                if (c0     > row0 + 8) s2 = -1e4f;
                if (c0 + 1 > row0 + 8) s3 = -1e4f;
            }
            float e0,e1,e2,e3;
            EX2F(e0, s0); EX2F(e1, s1); EX2F(e2, s2); EX2F(e3, s3);
            lsum_lo += e0 + e1;
            lsum_hi += e2 + e3;
            PKH2(plo[nf], e1, e0);
            PKH2(phi[nf], e3, e2);
        }

        // GEMM2: O += P · V (4 d-octet pairs, ping-ponged V fragments)
        const unsigned vb_lane = vbs + ((lane & 7) + (lane & 8))*144 + ((lane >> 4) & 1)*16;
#pragma unroll
        for (int j=0; j<4; j++){
            unsigned a[4] = {plo[2*j], phi[2*j], plo[2*j+1], phi[2*j+1]};
            unsigned vt[2][4];
            LDSM4T(vt[0][0], vt[0][1], vt[0][2], vt[0][3], vb_lane + j*16*144);
#pragma unroll
            for (int dd=0; dd<4; dd++){
                const int cur = dd & 1, nxt = cur ^ 1;
                if (dd < 3)
                    LDSM4T(vt[nxt][0], vt[nxt][1], vt[nxt][2], vt[nxt][3],
                           vb_lane + j*16*144 + (dd+1)*32);
                MMAH(o_acc[2*dd],   a, vt[cur][0], vt[cur][1]);
                MMAH(o_acc[2*dd+1], a, vt[cur][2], vt[cur][3]);
            }
        }
    }

    // epilogue: quad-reduce l, divide, store fp16
    lsum_lo += __shfl_xor_sync(0xffffffffu, lsum_lo, 1);
    lsum_lo += __shfl_xor_sync(0xffffffffu, lsum_lo, 2);
    lsum_hi += __shfl_xor_sync(0xffffffffu, lsum_hi, 1);
    lsum_hi += __shfl_xor_sync(0xffffffffu, lsum_hi, 2);
    const float i0 = 1.0f / lsum_lo;
    const float i1 = 1.0f / lsum_hi;
#pragma unroll
    for (int o=0; o<8; o++){
        const int col = h*64 + o*8 + (lane & 3)*2;
        *reinterpret_cast<__half2*>(g_o16 + (size_t)(bb*NT + row0)*NC + col)
            = __floats2half2_rn(o_acc[o][0]*i0, o_acc[o][1]*i0);
        *reinterpret_cast<__half2*>(g_o16 + (size_t)(bb*NT + row0 + 8)*NC + col)
            = __floats2half2_rn(o_acc[o][2]*i1, o_acc[o][3]*i1);
    }
}

// ======================================================================
extern "C" void kernel_launch(void* const* d_in, const int* in_sizes, int n_in,
                              void* d_out, int out_size)
{
    const float* x      = (const float*)d_in[0];
    const float* w_attn = (const float*)d_in[1];
    const float* b_attn = (const float*)d_in[2];
    const float* w_proj = (const float*)d_in[3];
    const float* b_proj = (const float*)d_in[4];
    float* out = (float*)d_out;

    cudaFuncSetAttribute(k_gemm16, cudaFuncAttributeMaxDynamicSharedMemorySize, GSMEM);
    cudaFuncSetAttribute(k_attn16, cudaFuncAttributeMaxDynamicSharedMemorySize, ASMEM);

    k_cvt16 <<<(NM*NC/4 + 255)/256, 256>>>(x, NM*NC/4);
    k_cvtT16<<<dim3(N3/32, NC/32), dim3(32,8)>>>(w_attn, N3, 0);
    k_cvtT16<<<dim3(NC/32, NC/32), dim3(32,8)>>>(w_proj, NC, 1);

    k_gemm16<<<dim3(N3/128, NM/128), 256, GSMEM>>>(b_attn, nullptr, 0);
    k_attn16<<<dim3(16, NB*NH), 256, ASMEM>>>();
    k_gemm16<<<dim3(NC/128, NM/128), 256, GSMEM>>>(b_proj, out, 1);
}

// round 17
// speedup vs baseline: 1.1366x; 1.1062x over previous
#include <cuda_runtime.h>
#include <cuda_fp16.h>
#include <math_constants.h>

#define NB 4
#define NT 2048
#define NC 1024
#define NH 16
#define ND 64
#define N3 (3*NC)
#define NM (NB*NT)

// ---------------- device-global scratch ----------------
__device__ __half g_x16[NM*NC];       // x fp16
__device__ __half g_wa16[N3*NC];      // w_attn^T fp16 [3072][1024]
__device__ __half g_wp16[NC*NC];      // w_proj^T fp16 [1024][1024]
__device__ __half g_q16[NB*NH*NT*ND]; // q * 0.125 * log2(e)
__device__ __half g_k16[NB*NH*NT*ND];
__device__ __half g_v16[NB*NH*NT*ND];
__device__ __half g_o16[NM*NC];       // attention out fp16 [M][1024]

__device__ __forceinline__ unsigned smem_u32(const void* p){
    unsigned a;
    asm("{ .reg .u64 t; cvta.to.shared.u64 t, %1; cvt.u32.u64 %0, t; }" : "=r"(a) : "l"(p));
    return a;
}

#define CPA16(s, g)  asm volatile("cp.async.cg.shared.global [%0], [%1], 16;" :: "r"(s), "l"(g))
#define CP_COMMIT()  asm volatile("cp.async.commit_group;" ::: "memory")
#define CP_WAIT1()   asm volatile("cp.async.wait_group 1;" ::: "memory")
#define CP_WAIT0()   asm volatile("cp.async.wait_group 0;" ::: "memory")

#define LDSM4(r0, r1, r2, r3, a) \
    asm volatile("ldmatrix.sync.aligned.m8n8.x4.shared.b16 {%0,%1,%2,%3}, [%4];" \
        : "=r"(r0), "=r"(r1), "=r"(r2), "=r"(r3) : "r"(a))
#define LDSM4T(r0, r1, r2, r3, a) \
    asm volatile("ldmatrix.sync.aligned.m8n8.x4.trans.shared.b16 {%0,%1,%2,%3}, [%4];" \
        : "=r"(r0), "=r"(r1), "=r"(r2), "=r"(r3) : "r"(a))

#define MMAH(c, a, b0, b1) \
    asm volatile("mma.sync.aligned.m16n8k16.row.col.f32.f16.f16.f32 " \
        "{%0,%1,%2,%3}, {%4,%5,%6,%7}, {%8,%9}, {%0,%1,%2,%3};" \
        : "+f"((c)[0]), "+f"((c)[1]), "+f"((c)[2]), "+f"((c)[3]) \
        : "r"((a)[0]), "r"((a)[1]), "r"((a)[2]), "r"((a)[3]), "r"(b0), "r"(b1))

#define PKH2(d, hi, lo) asm("cvt.rn.f16x2.f32 %0, %1, %2;" : "=r"(d) : "f"(hi), "f"(lo))
#define EX2F(d, a)      asm("ex2.approx.f32 %0, %1;" : "=f"(d) : "f"(a))

#define QSCALE 0.1803368801111204f   // 0.125 * log2(e)

// ======================================================================
// fp32 -> fp16 conversions
// ======================================================================
__global__ void __launch_bounds__(256) k_cvt16(const float* __restrict__ in, int n4)
{
    int i = blockIdx.x * blockDim.x + threadIdx.x;
    if (i >= n4) return;
    float4 v = reinterpret_cast<const float4*>(in)[i];
    reinterpret_cast<__half2*>(g_x16)[i*2]   = __floats2half2_rn(v.x, v.y);
    reinterpret_cast<__half2*>(g_x16)[i*2+1] = __floats2half2_rn(v.z, v.w);
}

__global__ void __launch_bounds__(256) k_cvtT16(const float* __restrict__ W, int Nn, int which)
{
    __shared__ float tile[32][33];
    __half* th = (which == 0) ? g_wa16 : g_wp16;
    int tx = threadIdx.x, ty = threadIdx.y;
    int n0 = blockIdx.x*32, k0 = blockIdx.y*32;
#pragma unroll
    for (int i=0;i<4;i++)
        tile[ty + i*8][tx] = W[(k0 + ty + i*8)*Nn + n0 + tx];
    __syncthreads();
#pragma unroll
    for (int i=0;i<4;i++)
        th[(n0 + ty + i*8)*NC + k0 + tx] = __float2half(tile[tx][ty + i*8]);
}

// ======================================================================
// fp16 GEMM: CTA 128x128, 256 threads (8 warps, 64x32), BK=64,
// 3-stage cp.async (110KB -> 2 CTAs/SM), fragment ping-pong,
// cp.async issue split into two phases interleaved with the ks loop.
// ======================================================================
#define TILE_B (128*144)        // 18432 bytes
#define STG    (2*TILE_B)       // 36864 (A + B)
#define GSMEM  (3*STG)          // 110592
#define NCH    16               // K/64

__device__ __forceinline__ void ld_half16(
    unsigned st, const __half* A, const __half* B, int m0, int n0, int c,
    int tid, int half)
{
    const int row = tid >> 1;
    const int ch0 = (tid & 1) * 4;
    const long aoff = (long)(m0 + row)*NC + c*64 + ch0*8;
    const long boff = (long)(n0 + row)*NC + c*64 + ch0*8;
    const unsigned sr = st + row*144 + ch0*16;
#pragma unroll
    for (int j=2*half; j<2*half+2; j++){
        CPA16(sr + j*16,          (const char*)(A + aoff + j*8));
        CPA16(sr + TILE_B + j*16, (const char*)(B + boff + j*8));
    }
}

__global__ void __launch_bounds__(256) k_gemm16(
    const float* __restrict__ bias, float* __restrict__ outp, int mode)
{
    extern __shared__ __align__(128) char smem[];
    const __half* A = (mode == 0) ? g_x16 : g_o16;
    const __half* B = (mode == 0) ? g_wa16 : g_wp16;
    const unsigned sb = smem_u32(smem);
    const int tid = threadIdx.x;
    const int wid = tid >> 5, lane = tid & 31;
    const int wm = wid >> 2, wn = wid & 3;
    const int m0 = blockIdx.y << 7;
    const int n0 = blockIdx.x << 7;

    float c[4][4][4];
#pragma unroll
    for (int i=0;i<4;i++)
#pragma unroll
        for (int j=0;j<4;j++){ c[i][j][0]=0.f; c[i][j][1]=0.f; c[i][j][2]=0.f; c[i][j][3]=0.f; }

    const unsigned a_base = (wm*64 + (lane & 15))*144 + (lane >> 4)*16;
    const unsigned b_base = (wn*32 + (lane & 7) + ((lane >> 1) & 8))*144 + (lane & 8)*2;

    ld_half16(sb, A, B, m0, n0, 0, tid, 0);
    ld_half16(sb, A, B, m0, n0, 0, tid, 1);
    CP_COMMIT();
    ld_half16(sb + STG, A, B, m0, n0, 1, tid, 0);
    ld_half16(sb + STG, A, B, m0, n0, 1, tid, 1);
    CP_COMMIT();

    for (int cc = 0; cc < NCH; cc++){
        if (cc == NCH-1) { CP_WAIT0(); } else { CP_WAIT1(); }
        __syncthreads();
        const unsigned st = sb + (cc%3)*STG;
        const unsigned pf = sb + ((cc+2)%3)*STG;
        const bool do_pf = (cc + 2 < NCH);

        unsigned ar[2][4][4], br[2][2][4];
#pragma unroll
        for (int mi=0; mi<4; mi++)
            LDSM4(ar[0][mi][0], ar[0][mi][1], ar[0][mi][2], ar[0][mi][3],
                  st + a_base + mi*16*144);
#pragma unroll
        for (int nb=0; nb<2; nb++)
            LDSM4(br[0][nb][0], br[0][nb][1], br[0][nb][2], br[0][nb][3],
                  st + TILE_B + b_base + nb*16*144);

        // ---- ks = 0 ----
#pragma unroll
        for (int mi=0; mi<4; mi++)
            LDSM4(ar[1][mi][0], ar[1][mi][1], ar[1][mi][2], ar[1][mi][3],
                  st + a_base + mi*16*144 + 32);
#pragma unroll
        for (int nb=0; nb<2; nb++)
            LDSM4(br[1][nb][0], br[1][nb][1], br[1][nb][2], br[1][nb][3],
                  st + TILE_B + b_base + nb*16*144 + 32);
#pragma unroll
        for (int mi=0; mi<4; mi++){
            MMAH(c[mi][0], ar[0][mi], br[0][0][0], br[0][0][1]);
            MMAH(c[mi][1], ar[0][mi], br[0][0][2], br[0][0][3]);
            MMAH(c[mi][2], ar[0][mi], br[0][1][0], br[0][1][1]);
            MMAH(c[mi][3], ar[0][mi], br[0][1][2], br[0][1][3]);
        }
        if (do_pf) ld_half16(pf, A, B, m0, n0, cc + 2, tid, 0);

        // ---- ks = 1 ----
#pragma unroll
        for (int mi=0; mi<4; mi++)
            LDSM4(ar[0][mi][0], ar[0][mi][1], ar[0][mi][2], ar[0][mi][3],
                  st + a_base + mi*16*144 + 64);
#pragma unroll
        for (int nb=0; nb<2; nb++)
            LDSM4(br[0][nb][0], br[0][nb][1], br[0][nb][2], br[0][nb][3],
                  st + TILE_B + b_base + nb*16*144 + 64);
#pragma unroll
        for (int mi=0; mi<4; mi++){
            MMAH(c[mi][0], ar[1][mi], br[1][0][0], br[1][0][1]);
            MMAH(c[mi][1], ar[1][mi], br[1][0][2], br[1][0][3]);
            MMAH(c[mi][2], ar[1][mi], br[1][1][0], br[1][1][1]);
            MMAH(c[mi][3], ar[1][mi], br[1][1][2], br[1][1][3]);
        }
        if (do_pf){ ld_half16(pf, A, B, m0, n0, cc + 2, tid, 1); CP_COMMIT(); }

        // ---- ks = 2 ----
#pragma unroll
        for (int mi=0; mi<4; mi++)
            LDSM4(ar[1][mi][0], ar[1][mi][1], ar[1][mi][2], ar[1][mi][3],
                  st + a_base + mi*16*144 + 96);
#pragma unroll
        for (int nb=0; nb<2; nb++)
            LDSM4(br[1][nb][0], br[1][nb][1], br[1][nb][2], br[1][nb][3],
                  st + TILE_B + b_base + nb*16*144 + 96);
#pragma unroll
        for (int mi=0; mi<4; mi++){
            MMAH(c[mi][0], ar[0][mi], br[0][0][0], br[0][0][1]);
            MMAH(c[mi][1], ar[0][mi], br[0][0][2], br[0][0][3]);
            MMAH(c[mi][2], ar[0][mi], br[0][1][0], br[0][1][1]);
            MMAH(c[mi][3], ar[0][mi], br[0][1][2], br[0][1][3]);
        }

        // ---- ks = 3 ----
#pragma unroll
        for (int mi=0; mi<4; mi++){
            MMAH(c[mi][0], ar[1][mi], br[1][0][0], br[1][0][1]);
            MMAH(c[mi][1], ar[1][mi], br[1][0][2], br[1][0][3]);
            MMAH(c[mi][2], ar[1][mi], br[1][1][0], br[1][1][1]);
            MMAH(c[mi][3], ar[1][mi], br[1][1][2], br[1][1][3]);
        }
        __syncthreads();
    }

    const int group = lane >> 2, tig = lane & 3;
#pragma unroll
    for (int mi=0; mi<4; mi++){
#pragma unroll
        for (int half=0; half<2; half++){
            const int m = m0 + wm*64 + mi*16 + group + half*8;
#pragma unroll
            for (int nf=0; nf<4; nf++){
                const int n = n0 + wn*32 + nf*8 + tig*2;
                float vx = c[mi][nf][half*2+0] + __ldg(&bias[n]);
                float vy = c[mi][nf][half*2+1] + __ldg(&bias[n+1]);
                if (mode == 1){
                    float2 v = {vx, vy};
                    *reinterpret_cast<float2*>(outp + (size_t)m*NC + n) = v;
                } else {
                    const int which = n >> 10;
                    const int cn = n & 1023;
                    const int h = cn >> 6, d = cn & 63;
                    const int bb = m >> 11, t = m & 2047;
                    __half* dst = (which == 0) ? g_q16 : (which == 1) ? g_k16 : g_v16;
                    if (which == 0){ vx *= QSCALE; vy *= QSCALE; }
                    *reinterpret_cast<__half2*>(dst + ((bb*NH + h)*NT + t)*ND + d)
                        = __floats2half2_rn(vx, vy);
                }
            }
        }
    }
}

// ======================================================================
// Tensor-core flash attention (R16 exact): l on the FMA pipe, V stride 144
// ======================================================================
#define SQ_OFF 0
#define SQ_STR 144
#define SK_OFF 18432
#define KSTG   9216
#define SV_OFF (SK_OFF + 3*KSTG)
#define VSTG   9216
#define ASMEM  (SV_OFF + 3*VSTG)     // 73728

__device__ __forceinline__ void ld_kv(unsigned kb, unsigned vb,
    const __half* kg, const __half* vg, int kt, int tid)
{
    const int r  = tid >> 2;
    const int c2 = (tid & 3) * 2;
    const char* kp = (const char*)(kg + (size_t)(kt*64 + r)*ND) + c2*16;
    const char* vp = (const char*)(vg + (size_t)(kt*64 + r)*ND) + c2*16;
    CPA16(kb + r*144 + c2*16,      kp);
    CPA16(kb + r*144 + c2*16 + 16, kp + 16);
    CPA16(vb + r*144 + c2*16,      vp);
    CPA16(vb + r*144 + c2*16 + 16, vp + 16);
}

__global__ void __launch_bounds__(256) k_attn16()
{
    extern __shared__ __align__(128) char smem[];
    const unsigned sb = smem_u32(smem);
    const int tid = threadIdx.x;
    const int wid = tid >> 5, lane = tid & 31;
    const int qb = 15 - blockIdx.x;
    const int bh = blockIdx.y;
    const int bb = bh >> 4, h = bh & 15;

    const __half* qg = g_q16 + (size_t)(bh*NT + qb*128)*ND;
    const __half* kg = g_k16 + (size_t)bh*NT*ND;
    const __half* vg = g_v16 + (size_t)bh*NT*ND;

#pragma unroll
    for (int i=0;i<4;i++){
        int idx = tid + i*256;
        int row = idx >> 3, ch = idx & 7;
        CPA16(sb + SQ_OFF + row*SQ_STR + ch*16, (const char*)(qg + row*ND) + ch*16);
    }
    ld_kv(sb + SK_OFF, sb + SV_OFF, kg, vg, 0, tid);
    CP_COMMIT();
    ld_kv(sb + SK_OFF + KSTG, sb + SV_OFF + VSTG, kg, vg, 1, tid);
    CP_COMMIT();
    CP_WAIT1();
    __syncthreads();

    unsigned aq[4][4];
    const unsigned qa = sb + SQ_OFF + (wid*16 + (lane & 15))*SQ_STR + (lane >> 4)*16;
#pragma unroll
    for (int ks=0; ks<4; ks++)
        LDSM4(aq[ks][0], aq[ks][1], aq[ks][2], aq[ks][3], qa + ks*32);

    float o_acc[8][4];
#pragma unroll
    for (int o=0;o<8;o++){ o_acc[o][0]=0.f; o_acc[o][1]=0.f; o_acc[o][2]=0.f; o_acc[o][3]=0.f; }
    float lsum_lo = 0.f, lsum_hi = 0.f;

    const int row0 = qb*128 + wid*16 + (lane >> 2);
    const int ktmax = 2*qb + 2;

    for (int kt = 0; kt < ktmax; kt++){
        if (kt > 0){
            if (kt == ktmax-1) { CP_WAIT0(); } else { CP_WAIT1(); }
            __syncthreads();
        }
        if (kt + 2 < ktmax){
            ld_kv(sb + SK_OFF + ((kt+2)%3)*KSTG, sb + SV_OFF + ((kt+2)%3)*VSTG,
                  kg, vg, kt+2, tid);
            CP_COMMIT();
        }

        const unsigned kbs = sb + SK_OFF + (kt%3)*KSTG;
        const unsigned vbs = sb + SV_OFF + (kt%3)*VSTG;

        float cS[8][4];
#pragma unroll
        for (int nf=0;nf<8;nf++){ cS[nf][0]=0.f; cS[nf][1]=0.f; cS[nf][2]=0.f; cS[nf][3]=0.f; }
        const unsigned kb_lane = kbs + ((lane & 7) + ((lane >> 1) & 8))*144 + (lane & 8)*2;
        {
            unsigned bkf[2][4];
            LDSM4(bkf[0][0], bkf[0][1], bkf[0][2], bkf[0][3], kb_lane);
#pragma unroll
            for (int s = 0; s < 16; s++){
                const int cur = s & 1, nxt = cur ^ 1;
                if (s < 15){
                    const int s1 = s + 1;
                    LDSM4(bkf[nxt][0], bkf[nxt][1], bkf[nxt][2], bkf[nxt][3],
                          kb_lane + (s1 & 3)*16*144 + (s1 >> 2)*32);
                }
                const int ks = s >> 2, nb = s & 3;
                MMAH(cS[2*nb],   aq[ks], bkf[cur][0], bkf[cur][1]);
                MMAH(cS[2*nb+1], aq[ks], bkf[cur][2], bkf[cur][3]);
            }
        }

        const bool masked = (kt >= 2*qb);
        unsigned plo[8], phi[8];
#pragma unroll
        for (int nf=0; nf<8; nf++){
            float s0 = cS[nf][0], s1 = cS[nf][1], s2 = cS[nf][2], s3 = cS[nf][3];
            if (masked){
                const int c0 = kt*64 + nf*8 + (lane & 3)*2;
                if (c0     > row0)     s0 = -1e4f;
                if (c0 + 1 > row0)     s1 = -1e4f;
                if (c0     > row0 + 8) s2 = -1e4f;
                if (c0 + 1 > row0 + 8) s3 = -1e4f;
            }
            float e0,e1,e2,e3;
            EX2F(e0, s0); EX2F(e1, s1); EX2F(e2, s2); EX2F(e3, s3);
            lsum_lo += e0 + e1;
            lsum_hi += e2 + e3;
            PKH2(plo[nf], e1, e0);
            PKH2(phi[nf], e3, e2);
        }

        const unsigned vb_lane = vbs + ((lane & 7) + (lane & 8))*144 + ((lane >> 4) & 1)*16;
#pragma unroll
        for (int j=0; j<4; j++){
            unsigned a[4] = {plo[2*j], phi[2*j], plo[2*j+1], phi[2*j+1]};
            unsigned vt[2][4];
            LDSM4T(vt[0][0], vt[0][1], vt[0][2], vt[0][3], vb_lane + j*16*144);
#pragma unroll
            for (int dd=0; dd<4; dd++){
                const int cur = dd & 1, nxt = cur ^ 1;
                if (dd < 3)
                    LDSM4T(vt[nxt][0], vt[nxt][1], vt[nxt][2], vt[nxt][3],
                           vb_lane + j*16*144 + (dd+1)*32);
                MMAH(o_acc[2*dd],   a, vt[cur][0], vt[cur][1]);
                MMAH(o_acc[2*dd+1], a, vt[cur][2], vt[cur][3]);
            }
        }
    }

    lsum_lo += __shfl_xor_sync(0xffffffffu, lsum_lo, 1);
    lsum_lo += __shfl_xor_sync(0xffffffffu, lsum_lo, 2);
    lsum_hi += __shfl_xor_sync(0xffffffffu, lsum_hi, 1);
    lsum_hi += __shfl_xor_sync(0xffffffffu, lsum_hi, 2);
    const float i0 = 1.0f / lsum_lo;
    const float i1 = 1.0f / lsum_hi;
#pragma unroll
    for (int o=0; o<8; o++){
        const int col = h*64 + o*8 + (lane & 3)*2;
        *reinterpret_cast<__half2*>(g_o16 + (size_t)(bb*NT + row0)*NC + col)
            = __floats2half2_rn(o_acc[o][0]*i0, o_acc[o][1]*i0);
        *reinterpret_cast<__half2*>(g_o16 + (size_t)(bb*NT + row0 + 8)*NC + col)
            = __floats2half2_rn(o_acc[o][2]*i1, o_acc[o][3]*i1);
    }
}

// ======================================================================
extern "C" void kernel_launch(void* const* d_in, const int* in_sizes, int n_in,
                              void* d_out, int out_size)
{
    const float* x      = (const float*)d_in[0];
    const float* w_attn = (const float*)d_in[1];
    const float* b_attn = (const float*)d_in[2];
    const float* w_proj = (const float*)d_in[3];
    const float* b_proj = (const float*)d_in[4];
    float* out = (float*)d_out;

    cudaFuncSetAttribute(k_gemm16, cudaFuncAttributeMaxDynamicSharedMemorySize, GSMEM);
    cudaFuncSetAttribute(k_attn16, cudaFuncAttributeMaxDynamicSharedMemorySize, ASMEM);

    k_cvt16 <<<(NM*NC/4 + 255)/256, 256>>>(x, NM*NC/4);
    k_cvtT16<<<dim3(N3/32, NC/32), dim3(32,8)>>>(w_attn, N3, 0);
    k_cvtT16<<<dim3(NC/32, NC/32), dim3(32,8)>>>(w_proj, NC, 1);

    k_gemm16<<<dim3(N3/128, NM/128), 256, GSMEM>>>(b_attn, nullptr, 0);
    k_attn16<<<dim3(16, NB*NH), 256, ASMEM>>>();
    k_gemm16<<<dim3(NC/128, NM/128), 256, GSMEM>>>(b_proj, out, 1);
}